// round 15
// baseline (speedup 1.0000x reference)
#include <cuda_runtime.h>
#include <cuda_bf16.h>
#include <cuda_fp16.h>
#include <math.h>
#include <math_constants.h>
#include <cstdint>

// Problem constants
#define BB 2
#define SS 2048
#define DD 1024
#define HH 16
#define DHH 64

// log2(e)/8  (folded into Q so softmax is pure 2^x)
#define QSCALE 0.18033688011112042f

// ---------------- device scratch (no cudaMalloc allowed) ----------------
__device__ __align__(16) __half g_xf[4096 * 1024];          // x, fp16
__device__ __align__(16) __half g_wf[3072 * 1024];          // wqkv, fp16
__device__ __align__(16) __half g_wof[1024 * 1024];         // wo, fp16
__device__ __align__(16) __half g_af[4096 * 1024];          // attn out, fp16

// Q (pre-scaled), K, V fp16 in [b][h][s][d] layout
__device__ __align__(16) __half g_qf[BB * HH * SS * DHH];
__device__ __align__(16) __half g_kf[BB * HH * SS * DHH];
__device__ __align__(16) __half g_vf[BB * HH * SS * DHH];

// ============================ helpers ============================
__device__ __forceinline__ uint32_t smem_u32(const void* p) {
    uint32_t a;
    asm("{ .reg .u64 t; cvta.to.shared.u64 t, %1; cvt.u32.u64 %0, t; }" : "=r"(a) : "l"(p));
    return a;
}

__device__ __forceinline__ void ldm_x4(uint32_t* r, uint32_t addr) {
    asm volatile("ldmatrix.sync.aligned.m8n8.x4.shared.b16 {%0,%1,%2,%3}, [%4];"
                 : "=r"(r[0]), "=r"(r[1]), "=r"(r[2]), "=r"(r[3]) : "r"(addr));
}
__device__ __forceinline__ void ldm_x4_t(uint32_t* r, uint32_t addr) {
    asm volatile("ldmatrix.sync.aligned.m8n8.x4.trans.shared.b16 {%0,%1,%2,%3}, [%4];"
                 : "=r"(r[0]), "=r"(r[1]), "=r"(r[2]), "=r"(r[3]) : "r"(addr));
}

// fp32-accumulate MMA
__device__ __forceinline__ void mma_f16(float* d, const uint32_t* a, const uint32_t* b) {
    asm volatile(
        "mma.sync.aligned.m16n8k16.row.col.f32.f16.f16.f32 "
        "{%0,%1,%2,%3}, {%4,%5,%6,%7}, {%8,%9}, {%0,%1,%2,%3};"
        : "+f"(d[0]), "+f"(d[1]), "+f"(d[2]), "+f"(d[3])
        : "r"(a[0]), "r"(a[1]), "r"(a[2]), "r"(a[3]), "r"(b[0]), "r"(b[1]));
}
// fp16-accumulate MMA (D,C = f16x2 pair)
__device__ __forceinline__ void mma_f16h(uint32_t* d, const uint32_t* a, const uint32_t* b) {
    asm volatile(
        "mma.sync.aligned.m16n8k16.row.col.f16.f16.f16.f16 "
        "{%0,%1}, {%2,%3,%4,%5}, {%6,%7}, {%0,%1};"
        : "+r"(d[0]), "+r"(d[1])
        : "r"(a[0]), "r"(a[1]), "r"(a[2]), "r"(a[3]), "r"(b[0]), "r"(b[1]));
}

__device__ __forceinline__ void cp16(uint32_t dst, const void* src) {
    asm volatile("cp.async.cg.shared.global [%0], [%1], 16;" :: "r"(dst), "l"(src));
}
#define CP_COMMIT() asm volatile("cp.async.commit_group;" ::: "memory")
#define CP_WAIT(n)  asm volatile("cp.async.wait_group %0;" :: "n"(n) : "memory")

__device__ __forceinline__ float ex2f(float x) {
    float y;
    asm("ex2.approx.ftz.f32 %0, %1;" : "=f"(y) : "f"(x));
    return y;
}
__device__ __forceinline__ uint32_t ex2h2(uint32_t x) {
    uint32_t y;
    asm("ex2.approx.f16x2 %0, %1;" : "=r"(y) : "r"(x));
    return y;
}
__device__ __forceinline__ uint32_t packh2(float a, float b) {
    __half2 h = __floats2half2_rn(a, b);
    return *(uint32_t*)&h;
}

// Prepass: fp32 -> fp16 (single)
__global__ __launch_bounds__(256) void convert_f16(const float4* __restrict__ src,
                                                   uint2* __restrict__ dst, int n4)
{
    for (int i = blockIdx.x * blockDim.x + threadIdx.x; i < n4; i += gridDim.x * blockDim.x) {
        float4 v = src[i];
        uint2 o;
        o.x = packh2(v.x, v.y);
        o.y = packh2(v.z, v.w);
        dst[i] = o;
    }
}

// Tile offset: two 64B k-rows packed per 128B SMEM line, SW128 swizzle (GEMM tiles).
__device__ __forceinline__ uint32_t toff(int r, int c) {
    uint32_t o = ((uint32_t)(r >> 1) << 7) | ((uint32_t)(r & 1) << 6) | ((uint32_t)c << 4);
    return o ^ ((o >> 3) & 0x70);
}
// 128B-row SW128 swizzle (attention tiles)
__device__ __forceinline__ uint32_t soff(int r, int c) {
    uint32_t o = (uint32_t)r * 128 + (uint32_t)c * 16;
    return o ^ ((o >> 3) & 0x70);
}

// ---------------------------------------------------------------------------
// fp16 GEMM NT with fp16 accumulation (4-MMA chains) + fp32 master:
// C[m,n] = sum_k A[m,k]*B[n,k], K=1024.
// 128x128 CTA tile, BK=32, 512 threads = 16 warps (2m x 8n), warp tile 64x16.
// 4-stage cp.async pipeline, one __syncthreads per chunk, 1 CTA/SM (16 warps).
// f16 accumulators flushed to fp32 every 2 chunks (K=64 per chain).
// MODE 0: C = fp32 out (proj).  MODE 1: QKV scatter epilogue (fp16 q/k/v).
// ---------------------------------------------------------------------------
#define GSMEM (4 * 16384)

template <int MODE>
__global__ __launch_bounds__(512) void gemm_f16(const __half* __restrict__ A,
                                                const __half* __restrict__ B,
                                                float* __restrict__ C, int N)
{
    extern __shared__ __align__(1024) uint8_t smem[];
    const uint32_t sb = smem_u32(smem);

    const int tid = threadIdx.x;
    const int lane = tid & 31;
    const int wid = tid >> 5;          // 0..15
    const int wm = wid & 1;            // 0..1
    const int wn = wid >> 1;           // 0..7
    const int bm = blockIdx.y * 128;
    const int bn = blockIdx.x * 128;

    // loads: 512 threads, each stages one 16B chunk of A and one of B per stage
    const int lr = tid >> 2;           // row 0..127
    const int lc = tid & 3;            // 16B-chunk 0..3
    const uint32_t so = toff(lr, lc);
    const __half* pA = A + (size_t)(bm + lr) * 1024 + lc * 8;
    const __half* pB = B + (size_t)(bn + lr) * 1024 + lc * 8;

    const int a_row = wm * 64 + (lane & 15);
    const int a_k16 = lane >> 4;
    const int b_row = wn * 16 + (lane & 7) + ((lane >> 4) & 1) * 8;
    const int b_k16 = (lane >> 3) & 1;

    float acc[4][2][4] = {};           // fp32 master
    uint32_t accH[4][2][2] = {};       // f16x2 chain accumulators

#pragma unroll
    for (int p = 0; p < 3; p++) {
        const uint32_t s = sb + p * 16384;
        const int ko = p * 32;
        cp16(s + so, pA + ko);
        cp16(s + 8192 + so, pB + ko);
        CP_COMMIT();
    }

    int slot = 0, nslot = 3;
    for (int kc = 0; kc < 32; kc++) {
        if (kc < 30) CP_WAIT(2);
        else if (kc == 30) CP_WAIT(1);
        else CP_WAIT(0);
        __syncthreads();

        if (kc + 3 < 32) {
            const uint32_t s = sb + nslot * 16384;
            const int ko = (kc + 3) * 32;
            cp16(s + so, pA + ko);
            cp16(s + 8192 + so, pB + ko);
            CP_COMMIT();
        }

        const uint32_t buf = sb + slot * 16384;
#pragma unroll
        for (int ks = 0; ks < 2; ks++) {
            uint32_t a[4][4], bfr[2][2];
#pragma unroll
            for (int mt = 0; mt < 4; mt++) {
                const uint32_t off = toff(a_row + mt * 16, ks * 2 + a_k16);
                ldm_x4(a[mt], buf + off);
            }
            {
                const uint32_t off = toff(b_row, ks * 2 + b_k16);
                uint32_t rh[4];
                ldm_x4(rh, buf + 8192 + off);
                bfr[0][0] = rh[0]; bfr[0][1] = rh[1];
                bfr[1][0] = rh[2]; bfr[1][1] = rh[3];
            }
#pragma unroll
            for (int mt = 0; mt < 4; mt++)
#pragma unroll
                for (int nt = 0; nt < 2; nt++)
                    mma_f16h(accH[mt][nt], a[mt], bfr[nt]);
        }

        // flush f16 chains to fp32 master every 2 chunks (K=64 per chain)
        if (kc & 1) {
#pragma unroll
            for (int mt = 0; mt < 4; mt++)
#pragma unroll
                for (int nt = 0; nt < 2; nt++) {
                    float2 f0 = __half22float2(*(__half2*)&accH[mt][nt][0]);
                    float2 f1 = __half22float2(*(__half2*)&accH[mt][nt][1]);
                    acc[mt][nt][0] += f0.x;
                    acc[mt][nt][1] += f0.y;
                    acc[mt][nt][2] += f1.x;
                    acc[mt][nt][3] += f1.y;
                    accH[mt][nt][0] = 0u;
                    accH[mt][nt][1] = 0u;
                }
        }

        slot = (slot == 3) ? 0 : slot + 1;
        nslot = (nslot == 3) ? 0 : nslot + 1;
    }

    if (MODE == 0) {
#pragma unroll
        for (int mt = 0; mt < 4; mt++) {
            const int r0 = bm + wm * 64 + mt * 16 + (lane >> 2);
#pragma unroll
            for (int nt = 0; nt < 2; nt++) {
                const int c = bn + wn * 16 + nt * 8 + (lane & 3) * 2;
                float2 v0 = {acc[mt][nt][0], acc[mt][nt][1]};
                float2 v1 = {acc[mt][nt][2], acc[mt][nt][3]};
                *(float2*)(C + (size_t)r0 * N + c) = v0;
                *(float2*)(C + (size_t)(r0 + 8) * N + c) = v1;
            }
        }
    } else {
        // QKV scatter: fp16 single, Q pre-scaled
#pragma unroll
        for (int mt = 0; mt < 4; mt++) {
            const int row = bm + wm * 64 + mt * 16 + (lane >> 2);
#pragma unroll
            for (int nt = 0; nt < 2; nt++) {
                const int c = bn + wn * 16 + nt * 8 + (lane & 3) * 2;
                const int which = c >> 10;
                const int hh = (c >> 6) & 15;
                const int d = c & 63;
#pragma unroll
                for (int half = 0; half < 2; half++) {
                    const int r = row + half * 8;
                    const int bb = r >> 11;
                    const int s = r & 2047;
                    const size_t idx = (((size_t)(bb * 16 + hh)) * SS + s) * 64 + d;
                    float v0 = acc[mt][nt][half * 2];
                    float v1 = acc[mt][nt][half * 2 + 1];
                    if (which == 0) {
                        *(uint32_t*)(g_qf + idx) = packh2(v0 * QSCALE, v1 * QSCALE);
                    } else if (which == 1) {
                        *(uint32_t*)(g_kf + idx) = packh2(v0, v1);
                    } else {
                        *(uint32_t*)(g_vf + idx) = packh2(v0, v1);
                    }
                }
            }
        }
    }
}

// ---------------------------------------------------------------------------
// Flash attention, all fp16 operands (R13, ties best).
// CTA = (qt, h, b), 256 thr, 8 warps x 16 q-rows. S/P in registers.
// SMEM: Q 16K | K bufs 2x8K | V bufs 2x8K = 48KB -> 2 CTAs/SM.
// ---------------------------------------------------------------------------
#define ASMEM 49152

__device__ __forceinline__ void attn_load_kv(uint32_t sb, size_t bh, int kt, int buf, int tid)
{
#pragma unroll
    for (int i = 0; i < 4; i++) {
        const int id = tid + 256 * i;
        const int t = id >> 9;        // 0 K, 1 V
        const int w = id & 511;
        const int r = w >> 3, c = w & 7;
        const uint32_t swz = soff(r, c);
        const size_t gidx = (bh * SS + (size_t)kt * 64 + r) * 64 + c * 8;
        if (t == 0) cp16(sb + 16384 + buf * 8192 + swz, g_kf + gidx);
        else        cp16(sb + 32768 + buf * 8192 + swz, g_vf + gidx);
    }
}

__global__ __launch_bounds__(256, 2) void attn_mma()
{
    extern __shared__ __align__(1024) uint8_t sm[];
    const uint32_t sb = smem_u32(sm);
    const int qt = (int)gridDim.x - 1 - (int)blockIdx.x;  // heavy tiles first
    const int h = blockIdx.y;
    const int b = blockIdx.z;
    const int tid = threadIdx.x;
    const int lane = tid & 31;
    const int wid = tid >> 5;
    const size_t bh = (size_t)(b * HH + h);
    const int nkt = 2 * qt + 2;

#pragma unroll
    for (int i = 0; i < 4; i++) {
        const int id = tid + 256 * i;
        const int r = id >> 3, c = id & 7;
        const size_t gidx = (bh * SS + (size_t)qt * 128 + r) * 64 + c * 8;
        cp16(sb + soff(r, c), g_qf + gidx);
    }
    attn_load_kv(sb, bh, 0, 0, tid);
    CP_COMMIT();
    attn_load_kv(sb, bh, 1, 1, tid);
    CP_COMMIT();

    float m1 = -CUDART_INF_F, m2 = -CUDART_INF_F;
    float o[8][4] = {};
    float lac[4] = {};
    const uint32_t ones2[2] = {0x3C003C00u, 0x3C003C00u};

    const int rg1 = qt * 128 + wid * 16 + (lane >> 2);

    for (int kt = 0; kt < nkt; kt++) {
        CP_WAIT(1);
        __syncthreads();

        const uint32_t kb = sb + 16384 + (kt & 1) * 8192;
        const uint32_t vb = sb + 32768 + (kt & 1) * 8192;

        const bool skipall = (kt == 2 * qt + 1) && (wid < 4);
        if (!skipall) {
            float s[8][4];
#pragma unroll
            for (int nt = 0; nt < 8; nt++)
#pragma unroll
                for (int j = 0; j < 4; j++) s[nt][j] = 0.f;

#pragma unroll
            for (int ks = 0; ks < 4; ks++) {
                uint32_t qa[4];
                const uint32_t offA = soff(wid * 16 + (lane & 15), ks * 2 + (lane >> 4));
                ldm_x4(qa, sb + offA);
#pragma unroll
                for (int nb = 0; nb < 4; nb++) {
                    const uint32_t offB = soff(nb * 16 + (lane & 7) + ((lane >> 4) & 1) * 8,
                                               ks * 2 + ((lane >> 3) & 1));
                    uint32_t rh[4];
                    ldm_x4(rh, kb + offB);
                    mma_f16(s[nb * 2], qa, rh);
                    mma_f16(s[nb * 2 + 1], qa, rh + 2);
                }
            }

            const bool domask = (kt == 2 * qt && wid < 4) || (kt == 2 * qt + 1 && wid >= 4);
            if (domask) {
#pragma unroll
                for (int nt = 0; nt < 8; nt++) {
                    const int cg = kt * 64 + nt * 8 + (lane & 3) * 2;
#pragma unroll
                    for (int j = 0; j < 4; j++) {
                        const int col = cg + (j & 1);
                        const int row = rg1 + ((j >> 1) << 3);
                        if (col > row) s[nt][j] = -1e30f;
                    }
                }
            }

            float t1 = -CUDART_INF_F, t2 = -CUDART_INF_F;
#pragma unroll
            for (int nt = 0; nt < 8; nt++) {
                t1 = fmaxf(t1, fmaxf(s[nt][0], s[nt][1]));
                t2 = fmaxf(t2, fmaxf(s[nt][2], s[nt][3]));
            }
            t1 = fmaxf(t1, __shfl_xor_sync(0xffffffffu, t1, 1));
            t1 = fmaxf(t1, __shfl_xor_sync(0xffffffffu, t1, 2));
            t2 = fmaxf(t2, __shfl_xor_sync(0xffffffffu, t2, 1));
            t2 = fmaxf(t2, __shfl_xor_sync(0xffffffffu, t2, 2));
            const float mn1 = fmaxf(m1, t1);
            const float mn2 = fmaxf(m2, t2);
            const float cr1 = ex2f(m1 - mn1);
            const float cr2 = ex2f(m2 - mn2);
            m1 = mn1; m2 = mn2;

            uint32_t p1[8], p2[8];
#pragma unroll
            for (int nt = 0; nt < 8; nt++) {
                p1[nt] = ex2h2(packh2(s[nt][0] - mn1, s[nt][1] - mn1));
                p2[nt] = ex2h2(packh2(s[nt][2] - mn2, s[nt][3] - mn2));
            }
#pragma unroll
            for (int nt = 0; nt < 8; nt++) {
                o[nt][0] *= cr1; o[nt][1] *= cr1;
                o[nt][2] *= cr2; o[nt][3] *= cr2;
            }
            lac[0] *= cr1; lac[1] *= cr1; lac[2] *= cr2; lac[3] *= cr2;

#pragma unroll
            for (int ks = 0; ks < 4; ks++) {
                uint32_t A[4] = {p1[ks * 2], p2[ks * 2], p1[ks * 2 + 1], p2[ks * 2 + 1]};
#pragma unroll
                for (int nb = 0; nb < 4; nb++) {
                    const uint32_t offV = soff(ks * 16 + (lane & 15), nb * 2 + (lane >> 4));
                    uint32_t vh[4];
                    ldm_x4_t(vh, vb + offV);
                    mma_f16(o[nb * 2], A, vh);
                    mma_f16(o[nb * 2 + 1], A, vh + 2);
                }
                mma_f16(lac, A, ones2);
            }
        }

        __syncthreads();
        if (kt + 2 < nkt) attn_load_kv(sb, bh, kt + 2, kt & 1, tid);
        CP_COMMIT();
    }

    const float inv1 = 1.f / lac[0];
    const float inv2 = 1.f / lac[2];
    const size_t tok1 = (size_t)(b * SS + qt * 128 + wid * 16 + (lane >> 2));
#pragma unroll
    for (int nt = 0; nt < 8; nt++) {
        const int col = h * 64 + nt * 8 + (lane & 3) * 2;
        *(uint32_t*)(g_af + tok1 * 1024 + col) = packh2(o[nt][0] * inv1, o[nt][1] * inv1);
        *(uint32_t*)(g_af + (tok1 + 8) * 1024 + col) = packh2(o[nt][2] * inv2, o[nt][3] * inv2);
    }
}

// ---------------------------------------------------------------------------
extern "C" void kernel_launch(void* const* d_in, const int* in_sizes, int n_in,
                              void* d_out, int out_size)
{
    const float* x    = (const float*)d_in[0];  // [2,2048,1024]
    const float* wqkv = (const float*)d_in[1];  // [3072,1024]
    const float* wo   = (const float*)d_in[2];  // [1024,1024]
    float* out = (float*)d_out;                 // [2,2048,1024]

    __half *xf, *wf, *wof, *af;
    cudaGetSymbolAddress((void**)&xf, g_xf);
    cudaGetSymbolAddress((void**)&wf, g_wf);
    cudaGetSymbolAddress((void**)&wof, g_wof);
    cudaGetSymbolAddress((void**)&af, g_af);

    cudaFuncSetAttribute(gemm_f16<0>, cudaFuncAttributeMaxDynamicSharedMemorySize, GSMEM);
    cudaFuncSetAttribute(gemm_f16<1>, cudaFuncAttributeMaxDynamicSharedMemorySize, GSMEM);
    cudaFuncSetAttribute(attn_mma, cudaFuncAttributeMaxDynamicSharedMemorySize, ASMEM);

    // Prepass conversions
    convert_f16<<<512, 256>>>((const float4*)x, (uint2*)xf, 4096 * 1024 / 4);
    convert_f16<<<512, 256>>>((const float4*)wqkv, (uint2*)wf, 3072 * 1024 / 4);
    convert_f16<<<256, 256>>>((const float4*)wo, (uint2*)wof, 1024 * 1024 / 4);

    // QKV = x @ wqkv^T with scatter epilogue -> g_qf/g_kf/g_vf
    gemm_f16<1><<<dim3(3072 / 128, 4096 / 128), 512, GSMEM>>>(xf, wf, nullptr, 3072);

    // Attention -> g_af (fp16)
    attn_mma<<<dim3(SS / 128, HH, BB), 256, ASMEM>>>();

    // out = attn @ wo^T
    gemm_f16<0><<<dim3(1024 / 128, 4096 / 128), 512, GSMEM>>>(af, wof, out, 1024);
}

// round 16
// speedup vs baseline: 1.1760x; 1.1760x over previous
#include <cuda_runtime.h>
#include <cuda_bf16.h>
#include <cuda_fp16.h>
#include <math.h>
#include <math_constants.h>
#include <cstdint>

// Problem constants
#define BB 2
#define SS 2048
#define DD 1024
#define HH 16
#define DHH 64

// log2(e)/8  (folded into Q so softmax is pure 2^x)
#define QSCALE 0.18033688011112042f

// ---------------- device scratch (no cudaMalloc allowed) ----------------
__device__ __align__(16) __half g_xf[4096 * 1024];          // x, fp16
__device__ __align__(16) __half g_wf[3072 * 1024];          // wqkv, fp16
__device__ __align__(16) __half g_wof[1024 * 1024];         // wo, fp16
__device__ __align__(16) __half g_af[4096 * 1024];          // attn out, fp16

// Q (pre-scaled), K, V fp16 in [b][h][s][d] layout
__device__ __align__(16) __half g_qf[BB * HH * SS * DHH];
__device__ __align__(16) __half g_kf[BB * HH * SS * DHH];
__device__ __align__(16) __half g_vf[BB * HH * SS * DHH];

// work-stealing counters: [0]=QKV gemm, [1]=proj gemm
__device__ int g_ctr[2];

// ============================ helpers ============================
__device__ __forceinline__ uint32_t smem_u32(const void* p) {
    uint32_t a;
    asm("{ .reg .u64 t; cvta.to.shared.u64 t, %1; cvt.u32.u64 %0, t; }" : "=r"(a) : "l"(p));
    return a;
}

__device__ __forceinline__ void ldm_x4(uint32_t* r, uint32_t addr) {
    asm volatile("ldmatrix.sync.aligned.m8n8.x4.shared.b16 {%0,%1,%2,%3}, [%4];"
                 : "=r"(r[0]), "=r"(r[1]), "=r"(r[2]), "=r"(r[3]) : "r"(addr));
}
__device__ __forceinline__ void ldm_x4_t(uint32_t* r, uint32_t addr) {
    asm volatile("ldmatrix.sync.aligned.m8n8.x4.trans.shared.b16 {%0,%1,%2,%3}, [%4];"
                 : "=r"(r[0]), "=r"(r[1]), "=r"(r[2]), "=r"(r[3]) : "r"(addr));
}

__device__ __forceinline__ void mma_f16(float* d, const uint32_t* a, const uint32_t* b) {
    asm volatile(
        "mma.sync.aligned.m16n8k16.row.col.f32.f16.f16.f32 "
        "{%0,%1,%2,%3}, {%4,%5,%6,%7}, {%8,%9}, {%0,%1,%2,%3};"
        : "+f"(d[0]), "+f"(d[1]), "+f"(d[2]), "+f"(d[3])
        : "r"(a[0]), "r"(a[1]), "r"(a[2]), "r"(a[3]), "r"(b[0]), "r"(b[1]));
}

__device__ __forceinline__ void cp16(uint32_t dst, const void* src) {
    asm volatile("cp.async.cg.shared.global [%0], [%1], 16;" :: "r"(dst), "l"(src));
}
#define CP_COMMIT() asm volatile("cp.async.commit_group;" ::: "memory")
#define CP_WAIT(n)  asm volatile("cp.async.wait_group %0;" :: "n"(n) : "memory")

__device__ __forceinline__ float ex2f(float x) {
    float y;
    asm("ex2.approx.ftz.f32 %0, %1;" : "=f"(y) : "f"(x));
    return y;
}
__device__ __forceinline__ uint32_t ex2h2(uint32_t x) {
    uint32_t y;
    asm("ex2.approx.f16x2 %0, %1;" : "=r"(y) : "r"(x));
    return y;
}
__device__ __forceinline__ uint32_t packh2(float a, float b) {
    __half2 h = __floats2half2_rn(a, b);
    return *(uint32_t*)&h;
}

// Prepass: fp32 -> fp16 (single)
__global__ __launch_bounds__(256) void convert_f16(const float4* __restrict__ src,
                                                   uint2* __restrict__ dst, int n4)
{
    for (int i = blockIdx.x * blockDim.x + threadIdx.x; i < n4; i += gridDim.x * blockDim.x) {
        float4 v = src[i];
        uint2 o;
        o.x = packh2(v.x, v.y);
        o.y = packh2(v.z, v.w);
        dst[i] = o;
    }
}

// Tile offset: two 64B k-rows packed per 128B SMEM line, SW128 swizzle (GEMM tiles).
__device__ __forceinline__ uint32_t toff(int r, int c) {
    uint32_t o = ((uint32_t)(r >> 1) << 7) | ((uint32_t)(r & 1) << 6) | ((uint32_t)c << 4);
    return o ^ ((o >> 3) & 0x70);
}
// 128B-row SW128 swizzle (attention tiles)
__device__ __forceinline__ uint32_t soff(int r, int c) {
    uint32_t o = (uint32_t)r * 128 + (uint32_t)c * 16;
    return o ^ ((o >> 3) & 0x70);
}

// ---------------------------------------------------------------------------
// Persistent fp16 GEMM NT (R10 math): C[m,n] = sum_k A[m,k]*B[n,k], K=1024.
// 128x128 tiles, BK=32, 8 warps (2m x 4n), warp tile 64x32, 2 CTAs/SM.
// Tiles pulled from a global atomic counter (kills wave-tail idle).
// MODE 0: C = fp32 out (proj).  MODE 1: QKV scatter epilogue (fp16 q/k/v).
// ---------------------------------------------------------------------------
#define GSMEM (4 * 16384 + 128)
#define GEMM_GRID 304

template <int MODE, int CIDX>
__global__ __launch_bounds__(256, 2) void gemm_f16(const __half* __restrict__ A,
                                                   const __half* __restrict__ B,
                                                   float* __restrict__ C,
                                                   int N, int ntiles)
{
    extern __shared__ __align__(1024) uint8_t smem[];
    const uint32_t sb = smem_u32(smem);
    int* tile_slot = (int*)(smem + 4 * 16384);

    const int tid = threadIdx.x;
    const int lane = tid & 31;
    const int wid = tid >> 5;
    const int wm = wid & 1;
    const int wn = wid >> 1;
    const int nbt = N >> 7;           // N-tiles per row

    const int m0 = tid >> 1;
    const int c0 = (tid & 1) * 2;
    const uint32_t so0 = toff(m0, c0);
    const uint32_t so1 = toff(m0, c0 + 1);

    const int a_row = wm * 64 + (lane & 15);
    const int a_k16 = lane >> 4;
    const int b_row = wn * 32 + (lane & 7) + ((lane >> 4) & 1) * 8;
    const int b_k16 = (lane >> 3) & 1;

    for (;;) {
        if (tid == 0) *tile_slot = atomicAdd(&g_ctr[CIDX], 1);
        __syncthreads();
        const int t = *tile_slot;
        if (t >= ntiles) return;

        const int bm = (t / nbt) * 128;
        const int bn = (t % nbt) * 128;
        const __half* pA = A + (size_t)(bm + m0) * 1024 + c0 * 8;
        const __half* pB = B + (size_t)(bn + m0) * 1024 + c0 * 8;

        float acc[4][4][4] = {};

#pragma unroll
        for (int p = 0; p < 3; p++) {
            const uint32_t s = sb + p * 16384;
            const int ko = p * 32;
            cp16(s + so0, pA + ko);          cp16(s + so1, pA + ko + 8);
            cp16(s + 8192 + so0, pB + ko);   cp16(s + 8192 + so1, pB + ko + 8);
            CP_COMMIT();
        }

        int slot = 0, nslot = 3;
        for (int kc = 0; kc < 32; kc++) {
            if (kc < 30) CP_WAIT(2);
            else if (kc == 30) CP_WAIT(1);
            else CP_WAIT(0);
            __syncthreads();

            if (kc + 3 < 32) {
                const uint32_t s = sb + nslot * 16384;
                const int ko = (kc + 3) * 32;
                cp16(s + so0, pA + ko);          cp16(s + so1, pA + ko + 8);
                cp16(s + 8192 + so0, pB + ko);   cp16(s + 8192 + so1, pB + ko + 8);
                CP_COMMIT();
            }

            const uint32_t buf = sb + slot * 16384;
#pragma unroll
            for (int ks = 0; ks < 2; ks++) {
                uint32_t a[4][4], bfr[4][2];
#pragma unroll
                for (int mt = 0; mt < 4; mt++) {
                    const uint32_t off = toff(a_row + mt * 16, ks * 2 + a_k16);
                    ldm_x4(a[mt], buf + off);
                }
#pragma unroll
                for (int nt2 = 0; nt2 < 2; nt2++) {
                    const uint32_t off = toff(b_row + nt2 * 16, ks * 2 + b_k16);
                    uint32_t rh[4];
                    ldm_x4(rh, buf + 8192 + off);
                    bfr[nt2 * 2][0] = rh[0]; bfr[nt2 * 2][1] = rh[1];
                    bfr[nt2 * 2 + 1][0] = rh[2]; bfr[nt2 * 2 + 1][1] = rh[3];
                }
#pragma unroll
                for (int mt = 0; mt < 4; mt++)
#pragma unroll
                    for (int nt = 0; nt < 4; nt++)
                        mma_f16(acc[mt][nt], a[mt], bfr[nt]);
            }
            slot = (slot == 3) ? 0 : slot + 1;
            nslot = (nslot == 3) ? 0 : nslot + 1;
        }

        if (MODE == 0) {
#pragma unroll
            for (int mt = 0; mt < 4; mt++) {
                const int r0 = bm + wm * 64 + mt * 16 + (lane >> 2);
#pragma unroll
                for (int nt = 0; nt < 4; nt++) {
                    const int c = bn + wn * 32 + nt * 8 + (lane & 3) * 2;
                    float2 v0 = {acc[mt][nt][0], acc[mt][nt][1]};
                    float2 v1 = {acc[mt][nt][2], acc[mt][nt][3]};
                    *(float2*)(C + (size_t)r0 * N + c) = v0;
                    *(float2*)(C + (size_t)(r0 + 8) * N + c) = v1;
                }
            }
        } else {
            // QKV scatter: fp16 single, Q pre-scaled
#pragma unroll
            for (int mt = 0; mt < 4; mt++) {
                const int row = bm + wm * 64 + mt * 16 + (lane >> 2);
#pragma unroll
                for (int nt = 0; nt < 4; nt++) {
                    const int c = bn + wn * 32 + nt * 8 + (lane & 3) * 2;
                    const int which = c >> 10;
                    const int hh = (c >> 6) & 15;
                    const int d = c & 63;
#pragma unroll
                    for (int half = 0; half < 2; half++) {
                        const int r = row + half * 8;
                        const int bb = r >> 11;
                        const int s = r & 2047;
                        const size_t idx = (((size_t)(bb * 16 + hh)) * SS + s) * 64 + d;
                        float v0 = acc[mt][nt][half * 2];
                        float v1 = acc[mt][nt][half * 2 + 1];
                        if (which == 0) {
                            *(uint32_t*)(g_qf + idx) = packh2(v0 * QSCALE, v1 * QSCALE);
                        } else if (which == 1) {
                            *(uint32_t*)(g_kf + idx) = packh2(v0, v1);
                        } else {
                            *(uint32_t*)(g_vf + idx) = packh2(v0, v1);
                        }
                    }
                }
            }
        }
        __syncthreads();  // all reads of tile_slot done before next overwrite
    }
}

// ---------------------------------------------------------------------------
// Flash attention, all fp16 operands (R13 — validated).
// CTA = (qt, h, b), 256 thr, 8 warps x 16 q-rows. S/P in registers.
// SMEM: Q 16K | K bufs 2x8K | V bufs 2x8K = 48KB -> 2 CTAs/SM.
// ---------------------------------------------------------------------------
#define ASMEM 49152

__device__ __forceinline__ void attn_load_kv(uint32_t sb, size_t bh, int kt, int buf, int tid)
{
#pragma unroll
    for (int i = 0; i < 4; i++) {
        const int id = tid + 256 * i;
        const int t = id >> 9;        // 0 K, 1 V
        const int w = id & 511;
        const int r = w >> 3, c = w & 7;
        const uint32_t swz = soff(r, c);
        const size_t gidx = (bh * SS + (size_t)kt * 64 + r) * 64 + c * 8;
        if (t == 0) cp16(sb + 16384 + buf * 8192 + swz, g_kf + gidx);
        else        cp16(sb + 32768 + buf * 8192 + swz, g_vf + gidx);
    }
}

__global__ __launch_bounds__(256, 2) void attn_mma()
{
    extern __shared__ __align__(1024) uint8_t sm[];
    const uint32_t sb = smem_u32(sm);
    const int qt = (int)gridDim.x - 1 - (int)blockIdx.x;  // heavy tiles first
    const int h = blockIdx.y;
    const int b = blockIdx.z;
    const int tid = threadIdx.x;
    const int lane = tid & 31;
    const int wid = tid >> 5;
    const size_t bh = (size_t)(b * HH + h);
    const int nkt = 2 * qt + 2;

#pragma unroll
    for (int i = 0; i < 4; i++) {
        const int id = tid + 256 * i;
        const int r = id >> 3, c = id & 7;
        const size_t gidx = (bh * SS + (size_t)qt * 128 + r) * 64 + c * 8;
        cp16(sb + soff(r, c), g_qf + gidx);
    }
    attn_load_kv(sb, bh, 0, 0, tid);
    CP_COMMIT();
    attn_load_kv(sb, bh, 1, 1, tid);
    CP_COMMIT();

    float m1 = -CUDART_INF_F, m2 = -CUDART_INF_F;
    float o[8][4] = {};
    float lac[4] = {};
    const uint32_t ones2[2] = {0x3C003C00u, 0x3C003C00u};

    const int rg1 = qt * 128 + wid * 16 + (lane >> 2);

    for (int kt = 0; kt < nkt; kt++) {
        CP_WAIT(1);
        __syncthreads();

        const uint32_t kb = sb + 16384 + (kt & 1) * 8192;
        const uint32_t vb = sb + 32768 + (kt & 1) * 8192;

        const bool skipall = (kt == 2 * qt + 1) && (wid < 4);
        if (!skipall) {
            float s[8][4];
#pragma unroll
            for (int nt = 0; nt < 8; nt++)
#pragma unroll
                for (int j = 0; j < 4; j++) s[nt][j] = 0.f;

#pragma unroll
            for (int ks = 0; ks < 4; ks++) {
                uint32_t qa[4];
                const uint32_t offA = soff(wid * 16 + (lane & 15), ks * 2 + (lane >> 4));
                ldm_x4(qa, sb + offA);
#pragma unroll
                for (int nb = 0; nb < 4; nb++) {
                    const uint32_t offB = soff(nb * 16 + (lane & 7) + ((lane >> 4) & 1) * 8,
                                               ks * 2 + ((lane >> 3) & 1));
                    uint32_t rh[4];
                    ldm_x4(rh, kb + offB);
                    mma_f16(s[nb * 2], qa, rh);
                    mma_f16(s[nb * 2 + 1], qa, rh + 2);
                }
            }

            const bool domask = (kt == 2 * qt && wid < 4) || (kt == 2 * qt + 1 && wid >= 4);
            if (domask) {
#pragma unroll
                for (int nt = 0; nt < 8; nt++) {
                    const int cg = kt * 64 + nt * 8 + (lane & 3) * 2;
#pragma unroll
                    for (int j = 0; j < 4; j++) {
                        const int col = cg + (j & 1);
                        const int row = rg1 + ((j >> 1) << 3);
                        if (col > row) s[nt][j] = -1e30f;
                    }
                }
            }

            float t1 = -CUDART_INF_F, t2 = -CUDART_INF_F;
#pragma unroll
            for (int nt = 0; nt < 8; nt++) {
                t1 = fmaxf(t1, fmaxf(s[nt][0], s[nt][1]));
                t2 = fmaxf(t2, fmaxf(s[nt][2], s[nt][3]));
            }
            t1 = fmaxf(t1, __shfl_xor_sync(0xffffffffu, t1, 1));
            t1 = fmaxf(t1, __shfl_xor_sync(0xffffffffu, t1, 2));
            t2 = fmaxf(t2, __shfl_xor_sync(0xffffffffu, t2, 1));
            t2 = fmaxf(t2, __shfl_xor_sync(0xffffffffu, t2, 2));
            const float mn1 = fmaxf(m1, t1);
            const float mn2 = fmaxf(m2, t2);
            const float cr1 = ex2f(m1 - mn1);
            const float cr2 = ex2f(m2 - mn2);
            m1 = mn1; m2 = mn2;

            uint32_t p1[8], p2[8];
#pragma unroll
            for (int nt = 0; nt < 8; nt++) {
                p1[nt] = ex2h2(packh2(s[nt][0] - mn1, s[nt][1] - mn1));
                p2[nt] = ex2h2(packh2(s[nt][2] - mn2, s[nt][3] - mn2));
            }
#pragma unroll
            for (int nt = 0; nt < 8; nt++) {
                o[nt][0] *= cr1; o[nt][1] *= cr1;
                o[nt][2] *= cr2; o[nt][3] *= cr2;
            }
            lac[0] *= cr1; lac[1] *= cr1; lac[2] *= cr2; lac[3] *= cr2;

#pragma unroll
            for (int ks = 0; ks < 4; ks++) {
                uint32_t A[4] = {p1[ks * 2], p2[ks * 2], p1[ks * 2 + 1], p2[ks * 2 + 1]};
#pragma unroll
                for (int nb = 0; nb < 4; nb++) {
                    const uint32_t offV = soff(ks * 16 + (lane & 15), nb * 2 + (lane >> 4));
                    uint32_t vh[4];
                    ldm_x4_t(vh, vb + offV);
                    mma_f16(o[nb * 2], A, vh);
                    mma_f16(o[nb * 2 + 1], A, vh + 2);
                }
                mma_f16(lac, A, ones2);
            }
        }

        __syncthreads();
        if (kt + 2 < nkt) attn_load_kv(sb, bh, kt + 2, kt & 1, tid);
        CP_COMMIT();
    }

    const float inv1 = 1.f / lac[0];
    const float inv2 = 1.f / lac[2];
    const size_t tok1 = (size_t)(b * SS + qt * 128 + wid * 16 + (lane >> 2));
#pragma unroll
    for (int nt = 0; nt < 8; nt++) {
        const int col = h * 64 + nt * 8 + (lane & 3) * 2;
        *(uint32_t*)(g_af + tok1 * 1024 + col) = packh2(o[nt][0] * inv1, o[nt][1] * inv1);
        *(uint32_t*)(g_af + (tok1 + 8) * 1024 + col) = packh2(o[nt][2] * inv2, o[nt][3] * inv2);
    }
}

// ---------------------------------------------------------------------------
extern "C" void kernel_launch(void* const* d_in, const int* in_sizes, int n_in,
                              void* d_out, int out_size)
{
    const float* x    = (const float*)d_in[0];  // [2,2048,1024]
    const float* wqkv = (const float*)d_in[1];  // [3072,1024]
    const float* wo   = (const float*)d_in[2];  // [1024,1024]
    float* out = (float*)d_out;                 // [2,2048,1024]

    __half *xf, *wf, *wof, *af;
    void* ctr;
    cudaGetSymbolAddress((void**)&xf, g_xf);
    cudaGetSymbolAddress((void**)&wf, g_wf);
    cudaGetSymbolAddress((void**)&wof, g_wof);
    cudaGetSymbolAddress((void**)&af, g_af);
    cudaGetSymbolAddress(&ctr, g_ctr);

    cudaFuncSetAttribute(gemm_f16<0, 1>, cudaFuncAttributeMaxDynamicSharedMemorySize, GSMEM);
    cudaFuncSetAttribute(gemm_f16<1, 0>, cudaFuncAttributeMaxDynamicSharedMemorySize, GSMEM);
    cudaFuncSetAttribute(attn_mma, cudaFuncAttributeMaxDynamicSharedMemorySize, ASMEM);

    // reset work-stealing counters (graph-capturable async memset)
    cudaMemsetAsync(ctr, 0, 2 * sizeof(int));

    // Prepass conversions
    convert_f16<<<512, 256>>>((const float4*)x, (uint2*)xf, 4096 * 1024 / 4);
    convert_f16<<<512, 256>>>((const float4*)wqkv, (uint2*)wf, 3072 * 1024 / 4);
    convert_f16<<<256, 256>>>((const float4*)wo, (uint2*)wof, 1024 * 1024 / 4);

    // QKV = x @ wqkv^T with scatter epilogue -> g_qf/g_kf/g_vf (persistent)
    gemm_f16<1, 0><<<GEMM_GRID, 256, GSMEM>>>(xf, wf, nullptr, 3072, 768);

    // Attention -> g_af (fp16)
    attn_mma<<<dim3(SS / 128, HH, BB), 256, ASMEM>>>();

    // out = attn @ wo^T (persistent; 256 tiles fit in one wave)
    gemm_f16<0, 1><<<GEMM_GRID, 256, GSMEM>>>(af, wof, out, 1024, 256);
}

// round 17
// speedup vs baseline: 1.2097x; 1.0286x over previous
#include <cuda_runtime.h>
#include <cuda_bf16.h>
#include <cuda_fp16.h>
#include <math.h>
#include <math_constants.h>
#include <cstdint>

// Problem constants
#define BB 2
#define SS 2048
#define DD 1024
#define HH 16
#define DHH 64

// log2(e)/8  (folded into Q so softmax is pure 2^x)
#define QSCALE 0.18033688011112042f

// ---------------- device scratch (no cudaMalloc allowed) ----------------
__device__ __align__(16) __half g_xf[4096 * 1024];          // x, fp16
__device__ __align__(16) __half g_wf[3072 * 1024];          // wqkv, fp16
__device__ __align__(16) __half g_wof[1024 * 1024];         // wo, fp16
__device__ __align__(16) __half g_af[4096 * 1024];          // attn out, fp16

// Q (pre-scaled), K, V fp16 in [b][h][s][d] layout
__device__ __align__(16) __half g_qf[BB * HH * SS * DHH];
__device__ __align__(16) __half g_kf[BB * HH * SS * DHH];
__device__ __align__(16) __half g_vf[BB * HH * SS * DHH];

// work-stealing counters: [0]=QKV gemm, [1]=proj gemm
__device__ int g_ctr[2];

// ============================ helpers ============================
__device__ __forceinline__ uint32_t smem_u32(const void* p) {
    uint32_t a;
    asm("{ .reg .u64 t; cvta.to.shared.u64 t, %1; cvt.u32.u64 %0, t; }" : "=r"(a) : "l"(p));
    return a;
}

__device__ __forceinline__ void ldm_x4(uint32_t* r, uint32_t addr) {
    asm volatile("ldmatrix.sync.aligned.m8n8.x4.shared.b16 {%0,%1,%2,%3}, [%4];"
                 : "=r"(r[0]), "=r"(r[1]), "=r"(r[2]), "=r"(r[3]) : "r"(addr));
}
__device__ __forceinline__ void ldm_x4_t(uint32_t* r, uint32_t addr) {
    asm volatile("ldmatrix.sync.aligned.m8n8.x4.trans.shared.b16 {%0,%1,%2,%3}, [%4];"
                 : "=r"(r[0]), "=r"(r[1]), "=r"(r[2]), "=r"(r[3]) : "r"(addr));
}

__device__ __forceinline__ void mma_f16(float* d, const uint32_t* a, const uint32_t* b) {
    asm volatile(
        "mma.sync.aligned.m16n8k16.row.col.f32.f16.f16.f32 "
        "{%0,%1,%2,%3}, {%4,%5,%6,%7}, {%8,%9}, {%0,%1,%2,%3};"
        : "+f"(d[0]), "+f"(d[1]), "+f"(d[2]), "+f"(d[3])
        : "r"(a[0]), "r"(a[1]), "r"(a[2]), "r"(a[3]), "r"(b[0]), "r"(b[1]));
}

__device__ __forceinline__ void cp16(uint32_t dst, const void* src) {
    asm volatile("cp.async.cg.shared.global [%0], [%1], 16;" :: "r"(dst), "l"(src));
}
#define CP_COMMIT() asm volatile("cp.async.commit_group;" ::: "memory")
#define CP_WAIT(n)  asm volatile("cp.async.wait_group %0;" :: "n"(n) : "memory")

__device__ __forceinline__ float ex2f(float x) {
    float y;
    asm("ex2.approx.ftz.f32 %0, %1;" : "=f"(y) : "f"(x));
    return y;
}
__device__ __forceinline__ uint32_t ex2h2(uint32_t x) {
    uint32_t y;
    asm("ex2.approx.f16x2 %0, %1;" : "=r"(y) : "r"(x));
    return y;
}
__device__ __forceinline__ uint32_t packh2(float a, float b) {
    __half2 h = __floats2half2_rn(a, b);
    return *(uint32_t*)&h;
}

// Fused prepass: fp32 -> fp16 for x, wqkv, wo in a single launch
#define N4_X  (4096 * 1024 / 4)
#define N4_W  (3072 * 1024 / 4)
#define N4_WO (1024 * 1024 / 4)
__global__ __launch_bounds__(256) void convert_all(const float4* __restrict__ x,
                                                   const float4* __restrict__ w,
                                                   const float4* __restrict__ wo,
                                                   uint2* __restrict__ xf,
                                                   uint2* __restrict__ wf,
                                                   uint2* __restrict__ wof)
{
    const int total = N4_X + N4_W + N4_WO;
    for (int i = blockIdx.x * blockDim.x + threadIdx.x; i < total; i += gridDim.x * blockDim.x) {
        const float4* src;
        uint2* dst;
        int j = i;
        if (j < N4_X) { src = x; dst = xf; }
        else if (j < N4_X + N4_W) { j -= N4_X; src = w; dst = wf; }
        else { j -= N4_X + N4_W; src = wo; dst = wof; }
        float4 v = src[j];
        uint2 o;
        o.x = packh2(v.x, v.y);
        o.y = packh2(v.z, v.w);
        dst[j] = o;
    }
}

// Tile offset: two 64B k-rows packed per 128B SMEM line, SW128 swizzle (GEMM tiles).
__device__ __forceinline__ uint32_t toff(int r, int c) {
    uint32_t o = ((uint32_t)(r >> 1) << 7) | ((uint32_t)(r & 1) << 6) | ((uint32_t)c << 4);
    return o ^ ((o >> 3) & 0x70);
}
// 128B-row SW128 swizzle (attention tiles)
__device__ __forceinline__ uint32_t soff(int r, int c) {
    uint32_t o = (uint32_t)r * 128 + (uint32_t)c * 16;
    return o ^ ((o >> 3) & 0x70);
}

// ---------------------------------------------------------------------------
// Persistent fp16 GEMM NT with CROSS-TILE software pipelining.
// C[m,n] = sum_k A[m,k]*B[n,k], K=1024. 128x128 tiles, BK=32, 8 warps,
// warp tile 64x32, 2 CTAs/SM. One commit_group per iteration (uniform
// CP_WAIT(2)); next tile's first 3 chunks are loaded during iterations
// kc=29..31, so the epilogue overlaps the next tile's prologue.
// MODE 0: C = fp32 out (proj).  MODE 1: QKV scatter epilogue (fp16 q/k/v).
// ---------------------------------------------------------------------------
#define GSMEM (4 * 16384 + 128)
#define GEMM_GRID 304

template <int MODE, int CIDX>
__global__ __launch_bounds__(256, 2) void gemm_f16(const __half* __restrict__ A,
                                                   const __half* __restrict__ B,
                                                   float* __restrict__ C,
                                                   int N, int ntiles)
{
    extern __shared__ __align__(1024) uint8_t smem[];
    const uint32_t sb = smem_u32(smem);
    int* tslot = (int*)(smem + 4 * 16384);   // [0]=cur tile, [1]=next tile

    const int tid = threadIdx.x;
    const int lane = tid & 31;
    const int wid = tid >> 5;
    const int wm = wid & 1;
    const int wn = wid >> 1;
    const int nbt = N >> 7;

    const int m0 = tid >> 1;
    const int c0 = (tid & 1) * 2;
    const uint32_t so0 = toff(m0, c0);
    const uint32_t so1 = toff(m0, c0 + 1);

    const int a_row = wm * 64 + (lane & 15);
    const int a_k16 = lane >> 4;
    const int b_row = wn * 32 + (lane & 7) + ((lane >> 4) & 1) * 8;
    const int b_k16 = (lane >> 3) & 1;

    if (tid == 0) tslot[0] = atomicAdd(&g_ctr[CIDX], 1);
    __syncthreads();
    int t = tslot[0];
    if (t >= ntiles) return;

    int bm = (t / nbt) * 128;
    int bn = (t % nbt) * 128;
    const __half* pA = A + (size_t)(bm + m0) * 1024 + c0 * 8;
    const __half* pB = B + (size_t)(bn + m0) * 1024 + c0 * 8;

    // prologue: first tile's chunks 0..2
#pragma unroll
    for (int p = 0; p < 3; p++) {
        const uint32_t s = sb + p * 16384;
        const int ko = p * 32;
        cp16(s + so0, pA + ko);          cp16(s + so1, pA + ko + 8);
        cp16(s + 8192 + so0, pB + ko);   cp16(s + 8192 + so1, pB + ko + 8);
        CP_COMMIT();
    }

    int slot = 0, nslot = 3;
    for (;;) {
        float acc[4][4][4] = {};

        for (int kc = 0; kc < 32; kc++) {
            CP_WAIT(2);
            __syncthreads();

            if (tid == 0 && kc == 27) tslot[1] = atomicAdd(&g_ctr[CIDX], 1);

            const uint32_t s = sb + nslot * 16384;
            if (kc < 29) {
                const int ko = (kc + 3) * 32;
                cp16(s + so0, pA + ko);          cp16(s + so1, pA + ko + 8);
                cp16(s + 8192 + so0, pB + ko);   cp16(s + 8192 + so1, pB + ko + 8);
            } else {
                const int t2 = tslot[1];   // written at kc==27, ordered by kc>=28 barriers
                if (t2 < ntiles) {
                    const int ko = (kc - 29) * 32;
                    const __half* qA = A + (size_t)(((t2 / nbt) << 7) + m0) * 1024 + c0 * 8 + ko;
                    const __half* qB = B + (size_t)(((t2 % nbt) << 7) + m0) * 1024 + c0 * 8 + ko;
                    cp16(s + so0, qA);          cp16(s + so1, qA + 8);
                    cp16(s + 8192 + so0, qB);   cp16(s + 8192 + so1, qB + 8);
                }
            }
            CP_COMMIT();   // exactly one group per iteration (may be empty)

            const uint32_t buf = sb + slot * 16384;
#pragma unroll
            for (int ks = 0; ks < 2; ks++) {
                uint32_t a[4][4], bfr[4][2];
#pragma unroll
                for (int mt = 0; mt < 4; mt++) {
                    const uint32_t off = toff(a_row + mt * 16, ks * 2 + a_k16);
                    ldm_x4(a[mt], buf + off);
                }
#pragma unroll
                for (int nt2 = 0; nt2 < 2; nt2++) {
                    const uint32_t off = toff(b_row + nt2 * 16, ks * 2 + b_k16);
                    uint32_t rh[4];
                    ldm_x4(rh, buf + 8192 + off);
                    bfr[nt2 * 2][0] = rh[0]; bfr[nt2 * 2][1] = rh[1];
                    bfr[nt2 * 2 + 1][0] = rh[2]; bfr[nt2 * 2 + 1][1] = rh[3];
                }
#pragma unroll
                for (int mt = 0; mt < 4; mt++)
#pragma unroll
                    for (int nt = 0; nt < 4; nt++)
                        mma_f16(acc[mt][nt], a[mt], bfr[nt]);
            }
            slot = (slot == 3) ? 0 : slot + 1;
            nslot = (nslot == 3) ? 0 : nslot + 1;
        }

        // epilogue (overlaps the already-in-flight next-tile prologue)
        if (MODE == 0) {
#pragma unroll
            for (int mt = 0; mt < 4; mt++) {
                const int r0 = bm + wm * 64 + mt * 16 + (lane >> 2);
#pragma unroll
                for (int nt = 0; nt < 4; nt++) {
                    const int c = bn + wn * 32 + nt * 8 + (lane & 3) * 2;
                    float2 v0 = {acc[mt][nt][0], acc[mt][nt][1]};
                    float2 v1 = {acc[mt][nt][2], acc[mt][nt][3]};
                    *(float2*)(C + (size_t)r0 * N + c) = v0;
                    *(float2*)(C + (size_t)(r0 + 8) * N + c) = v1;
                }
            }
        } else {
#pragma unroll
            for (int mt = 0; mt < 4; mt++) {
                const int row = bm + wm * 64 + mt * 16 + (lane >> 2);
#pragma unroll
                for (int nt = 0; nt < 4; nt++) {
                    const int c = bn + wn * 32 + nt * 8 + (lane & 3) * 2;
                    const int which = c >> 10;
                    const int hh = (c >> 6) & 15;
                    const int d = c & 63;
#pragma unroll
                    for (int half = 0; half < 2; half++) {
                        const int r = row + half * 8;
                        const int bb = r >> 11;
                        const int s = r & 2047;
                        const size_t idx = (((size_t)(bb * 16 + hh)) * SS + s) * 64 + d;
                        float v0 = acc[mt][nt][half * 2];
                        float v1 = acc[mt][nt][half * 2 + 1];
                        if (which == 0) {
                            *(uint32_t*)(g_qf + idx) = packh2(v0 * QSCALE, v1 * QSCALE);
                        } else if (which == 1) {
                            *(uint32_t*)(g_kf + idx) = packh2(v0, v1);
                        } else {
                            *(uint32_t*)(g_vf + idx) = packh2(v0, v1);
                        }
                    }
                }
            }
        }

        const int t2 = tslot[1];
        if (t2 >= ntiles) return;
        t = t2;
        bm = (t / nbt) * 128;
        bn = (t % nbt) * 128;
        pA = A + (size_t)(bm + m0) * 1024 + c0 * 8;
        pB = B + (size_t)(bn + m0) * 1024 + c0 * 8;
        // chunks 0..2 of this tile are already in flight; mainloop continues.
    }
}

// ---------------------------------------------------------------------------
// Flash attention, all fp16 operands (R13 — validated).
// CTA = (qt, h, b), 256 thr, 8 warps x 16 q-rows. S/P in registers.
// SMEM: Q 16K | K bufs 2x8K | V bufs 2x8K = 48KB -> 2 CTAs/SM.
// ---------------------------------------------------------------------------
#define ASMEM 49152

__device__ __forceinline__ void attn_load_kv(uint32_t sb, size_t bh, int kt, int buf, int tid)
{
#pragma unroll
    for (int i = 0; i < 4; i++) {
        const int id = tid + 256 * i;
        const int t = id >> 9;        // 0 K, 1 V
        const int w = id & 511;
        const int r = w >> 3, c = w & 7;
        const uint32_t swz = soff(r, c);
        const size_t gidx = (bh * SS + (size_t)kt * 64 + r) * 64 + c * 8;
        if (t == 0) cp16(sb + 16384 + buf * 8192 + swz, g_kf + gidx);
        else        cp16(sb + 32768 + buf * 8192 + swz, g_vf + gidx);
    }
}

__global__ __launch_bounds__(256, 2) void attn_mma()
{
    extern __shared__ __align__(1024) uint8_t sm[];
    const uint32_t sb = smem_u32(sm);
    const int qt = (int)gridDim.x - 1 - (int)blockIdx.x;  // heavy tiles first
    const int h = blockIdx.y;
    const int b = blockIdx.z;
    const int tid = threadIdx.x;
    const int lane = tid & 31;
    const int wid = tid >> 5;
    const size_t bh = (size_t)(b * HH + h);
    const int nkt = 2 * qt + 2;

#pragma unroll
    for (int i = 0; i < 4; i++) {
        const int id = tid + 256 * i;
        const int r = id >> 3, c = id & 7;
        const size_t gidx = (bh * SS + (size_t)qt * 128 + r) * 64 + c * 8;
        cp16(sb + soff(r, c), g_qf + gidx);
    }
    attn_load_kv(sb, bh, 0, 0, tid);
    CP_COMMIT();
    attn_load_kv(sb, bh, 1, 1, tid);
    CP_COMMIT();

    float m1 = -CUDART_INF_F, m2 = -CUDART_INF_F;
    float o[8][4] = {};
    float lac[4] = {};
    const uint32_t ones2[2] = {0x3C003C00u, 0x3C003C00u};

    const int rg1 = qt * 128 + wid * 16 + (lane >> 2);

    for (int kt = 0; kt < nkt; kt++) {
        CP_WAIT(1);
        __syncthreads();

        const uint32_t kb = sb + 16384 + (kt & 1) * 8192;
        const uint32_t vb = sb + 32768 + (kt & 1) * 8192;

        const bool skipall = (kt == 2 * qt + 1) && (wid < 4);
        if (!skipall) {
            float s[8][4];
#pragma unroll
            for (int nt = 0; nt < 8; nt++)
#pragma unroll
                for (int j = 0; j < 4; j++) s[nt][j] = 0.f;

#pragma unroll
            for (int ks = 0; ks < 4; ks++) {
                uint32_t qa[4];
                const uint32_t offA = soff(wid * 16 + (lane & 15), ks * 2 + (lane >> 4));
                ldm_x4(qa, sb + offA);
#pragma unroll
                for (int nb = 0; nb < 4; nb++) {
                    const uint32_t offB = soff(nb * 16 + (lane & 7) + ((lane >> 4) & 1) * 8,
                                               ks * 2 + ((lane >> 3) & 1));
                    uint32_t rh[4];
                    ldm_x4(rh, kb + offB);
                    mma_f16(s[nb * 2], qa, rh);
                    mma_f16(s[nb * 2 + 1], qa, rh + 2);
                }
            }

            const bool domask = (kt == 2 * qt && wid < 4) || (kt == 2 * qt + 1 && wid >= 4);
            if (domask) {
#pragma unroll
                for (int nt = 0; nt < 8; nt++) {
                    const int cg = kt * 64 + nt * 8 + (lane & 3) * 2;
#pragma unroll
                    for (int j = 0; j < 4; j++) {
                        const int col = cg + (j & 1);
                        const int row = rg1 + ((j >> 1) << 3);
                        if (col > row) s[nt][j] = -1e30f;
                    }
                }
            }

            float t1 = -CUDART_INF_F, t2 = -CUDART_INF_F;
#pragma unroll
            for (int nt = 0; nt < 8; nt++) {
                t1 = fmaxf(t1, fmaxf(s[nt][0], s[nt][1]));
                t2 = fmaxf(t2, fmaxf(s[nt][2], s[nt][3]));
            }
            t1 = fmaxf(t1, __shfl_xor_sync(0xffffffffu, t1, 1));
            t1 = fmaxf(t1, __shfl_xor_sync(0xffffffffu, t1, 2));
            t2 = fmaxf(t2, __shfl_xor_sync(0xffffffffu, t2, 1));
            t2 = fmaxf(t2, __shfl_xor_sync(0xffffffffu, t2, 2));
            const float mn1 = fmaxf(m1, t1);
            const float mn2 = fmaxf(m2, t2);
            const float cr1 = ex2f(m1 - mn1);
            const float cr2 = ex2f(m2 - mn2);
            m1 = mn1; m2 = mn2;

            uint32_t p1[8], p2[8];
#pragma unroll
            for (int nt = 0; nt < 8; nt++) {
                p1[nt] = ex2h2(packh2(s[nt][0] - mn1, s[nt][1] - mn1));
                p2[nt] = ex2h2(packh2(s[nt][2] - mn2, s[nt][3] - mn2));
            }
#pragma unroll
            for (int nt = 0; nt < 8; nt++) {
                o[nt][0] *= cr1; o[nt][1] *= cr1;
                o[nt][2] *= cr2; o[nt][3] *= cr2;
            }
            lac[0] *= cr1; lac[1] *= cr1; lac[2] *= cr2; lac[3] *= cr2;

#pragma unroll
            for (int ks = 0; ks < 4; ks++) {
                uint32_t A[4] = {p1[ks * 2], p2[ks * 2], p1[ks * 2 + 1], p2[ks * 2 + 1]};
#pragma unroll
                for (int nb = 0; nb < 4; nb++) {
                    const uint32_t offV = soff(ks * 16 + (lane & 15), nb * 2 + (lane >> 4));
                    uint32_t vh[4];
                    ldm_x4_t(vh, vb + offV);
                    mma_f16(o[nb * 2], A, vh);
                    mma_f16(o[nb * 2 + 1], A, vh + 2);
                }
                mma_f16(lac, A, ones2);
            }
        }

        __syncthreads();
        if (kt + 2 < nkt) attn_load_kv(sb, bh, kt + 2, kt & 1, tid);
        CP_COMMIT();
    }

    const float inv1 = 1.f / lac[0];
    const float inv2 = 1.f / lac[2];
    const size_t tok1 = (size_t)(b * SS + qt * 128 + wid * 16 + (lane >> 2));
#pragma unroll
    for (int nt = 0; nt < 8; nt++) {
        const int col = h * 64 + nt * 8 + (lane & 3) * 2;
        *(uint32_t*)(g_af + tok1 * 1024 + col) = packh2(o[nt][0] * inv1, o[nt][1] * inv1);
        *(uint32_t*)(g_af + (tok1 + 8) * 1024 + col) = packh2(o[nt][2] * inv2, o[nt][3] * inv2);
    }
}

// ---------------------------------------------------------------------------
extern "C" void kernel_launch(void* const* d_in, const int* in_sizes, int n_in,
                              void* d_out, int out_size)
{
    const float* x    = (const float*)d_in[0];  // [2,2048,1024]
    const float* wqkv = (const float*)d_in[1];  // [3072,1024]
    const float* wo   = (const float*)d_in[2];  // [1024,1024]
    float* out = (float*)d_out;                 // [2,2048,1024]

    __half *xf, *wf, *wof, *af;
    void* ctr;
    cudaGetSymbolAddress((void**)&xf, g_xf);
    cudaGetSymbolAddress((void**)&wf, g_wf);
    cudaGetSymbolAddress((void**)&wof, g_wof);
    cudaGetSymbolAddress((void**)&af, g_af);
    cudaGetSymbolAddress(&ctr, g_ctr);

    cudaFuncSetAttribute(gemm_f16<0, 1>, cudaFuncAttributeMaxDynamicSharedMemorySize, GSMEM);
    cudaFuncSetAttribute(gemm_f16<1, 0>, cudaFuncAttributeMaxDynamicSharedMemorySize, GSMEM);
    cudaFuncSetAttribute(attn_mma, cudaFuncAttributeMaxDynamicSharedMemorySize, ASMEM);

    // reset work-stealing counters (graph-capturable async memset)
    cudaMemsetAsync(ctr, 0, 2 * sizeof(int));

    // Fused prepass conversion (single launch)
    convert_all<<<1024, 256>>>((const float4*)x, (const float4*)wqkv, (const float4*)wo,
                               (uint2*)xf, (uint2*)wf, (uint2*)wof);

    // QKV = x @ wqkv^T with scatter epilogue -> g_qf/g_kf/g_vf (persistent)
    gemm_f16<1, 0><<<GEMM_GRID, 256, GSMEM>>>(xf, wf, nullptr, 3072, 768);

    // Attention -> g_af (fp16)
    attn_mma<<<dim3(SS / 128, HH, BB), 256, ASMEM>>>();

    // out = attn @ wo^T (persistent)
    gemm_f16<0, 1><<<GEMM_GRID, 256, GSMEM>>>(af, wof, out, 1024, 256);
}